// round 17
// baseline (speedup 1.0000x reference)
#include <cuda_runtime.h>
#include <cuda_fp16.h>
#include <math.h>
#include <stdint.h>

// ---------------- problem constants ----------------
#define BB 4
#define CC 3
#define HH 224
#define WW 224
#define PP 16
#define EE 768
#define NHH 12
#define DHH 64
#define LL 2
#define DFF_ 3072
#define OUTC 1000
#define NPAT 196
#define TT 197
#define MROWS (BB*TT)      // 788
#define KPATCH (CC*PP*PP)  // 768
#define IM2COL_TOTAL (BB*NPAT*KPATCH)   // 602112

// fp16 weight layout (elements), all [K][N] row-major
#define SZ_PATCH_H 589824
#define SZ_QKV_H   1769472
#define SZ_PROJ_H  589824
#define SZ_FC1_H   2359296
#define SZ_FC2_H   2359296
#define SZ_LAYER_H 7077888
#define W_TOTAL_H  (SZ_PATCH_H + 2*SZ_LAYER_H)   // 14745600

#define G_PART_SZ 4534272

// ---------------- scratch ----------------
__device__ float g_h[MROWS*EE];
__device__ float g_part[G_PART_SZ];    // split-K partials / qkv (fp32, bias included)
__device__ __half g_act[MROWS*DFF_];   // im2col / attn-out / fc1-out (fp16)
__device__ __half g_lnh[MROWS*EE];     // LN output (fp16)
__device__ __half g_wh[W_TOTAL_H];     // all weights fp16 [K][N]

// ---------------- helpers ----------------
__device__ __forceinline__ uint32_t smaddr(const void* p) {
    return (uint32_t)__cvta_generic_to_shared(p);
}
__device__ __forceinline__ void ldsm_x4(uint32_t& r0, uint32_t& r1, uint32_t& r2, uint32_t& r3, uint32_t a) {
    asm volatile("ldmatrix.sync.aligned.m8n8.x4.shared.b16 {%0,%1,%2,%3}, [%4];"
                 : "=r"(r0), "=r"(r1), "=r"(r2), "=r"(r3) : "r"(a));
}
__device__ __forceinline__ void ldsm_x4_t(uint32_t& r0, uint32_t& r1, uint32_t& r2, uint32_t& r3, uint32_t a) {
    asm volatile("ldmatrix.sync.aligned.m8n8.x4.trans.shared.b16 {%0,%1,%2,%3}, [%4];"
                 : "=r"(r0), "=r"(r1), "=r"(r2), "=r"(r3) : "r"(a));
}
__device__ __forceinline__ void mma_f16(float* c, const uint32_t* a, uint32_t b0, uint32_t b1) {
    asm volatile("mma.sync.aligned.m16n8k16.row.col.f32.f16.f16.f32 "
                 "{%0,%1,%2,%3}, {%4,%5,%6,%7}, {%8,%9}, {%0,%1,%2,%3};"
                 : "+f"(c[0]), "+f"(c[1]), "+f"(c[2]), "+f"(c[3])
                 : "r"(a[0]), "r"(a[1]), "r"(a[2]), "r"(a[3]), "r"(b0), "r"(b1));
}
__device__ __forceinline__ float gelu_tanh(float v) {
    float v3 = v * v * v;
    return 0.5f * v * (1.0f + tanhf(0.7978845608028654f * (v + 0.044715f * v3)));
}
__device__ __forceinline__ float block_sum(float v, float* red, int tid) {
    red[tid] = v; __syncthreads();
    for (int st = 128; st > 0; st >>= 1) { if (tid < st) red[tid] += red[tid + st]; __syncthreads(); }
    float r = red[0]; __syncthreads();
    return r;
}

// ---------------- merged prep: im2col -> fp16 AND weight conversion ----------------
__global__ void prep_kernel(const float* __restrict__ x,
                            const float* __restrict__ conv_w, const float* __restrict__ attn_w,
                            const float* __restrict__ proj_w, const float* __restrict__ fc1_w,
                            const float* __restrict__ fc2_w) {
    int idx = blockIdx.x * blockDim.x + threadIdx.x;
    if (idx < IM2COL_TOTAL) {
        int k   = idx % KPATCH;
        int row = idx / KPATCH;
        int b = row / NPAT, t = row % NPAT;
        int ph = t / 14, pw = t % 14;
        int c = k / (PP*PP);
        int r = (k % (PP*PP)) / PP;
        int q = k % PP;
        g_act[idx] = __float2half(x[(((size_t)(b*CC + c)*HH) + ph*PP + r) * WW + pw*PP + q]);
        return;
    }
    idx -= IM2COL_TOTAL;
    if (idx >= W_TOTAL_H) return;
    if (idx < SZ_PATCH_H) {
        int k = idx / EE, n = idx % EE;
        g_wh[idx] = __float2half(conv_w[(size_t)n*KPATCH + k]);
        return;
    }
    int r = idx - SZ_PATCH_H;
    int l = r / SZ_LAYER_H; r %= SZ_LAYER_H;
    const float* src;
    if (r < SZ_QKV_H) { src = attn_w + (size_t)l*SZ_QKV_H + r; }
    else if (r < SZ_QKV_H + SZ_PROJ_H) { src = proj_w + (size_t)l*SZ_PROJ_H + (r - SZ_QKV_H); }
    else if (r < SZ_QKV_H + SZ_PROJ_H + SZ_FC1_H) { src = fc1_w + (size_t)l*SZ_FC1_H + (r - SZ_QKV_H - SZ_PROJ_H); }
    else { src = fc2_w + (size_t)l*SZ_FC2_H + (r - SZ_QKV_H - SZ_PROJ_H - SZ_FC1_H); }
    g_wh[idx] = __float2half(*src);
}

// ---------------- patch epilogue: reduce(3) + assemble + LN (fp16 out) ----------------
__global__ void patch_ln_kernel(const float* __restrict__ part, const float* __restrict__ conv_b,
                                const float* __restrict__ pos_embed, const float* __restrict__ cls_token,
                                const float* __restrict__ lw, const float* __restrict__ lb) {
    int r = blockIdx.x;
    int b = r / TT, t = r % TT;
    int tid = threadIdx.x;
    __shared__ float red[256];
    float v[3];
    #pragma unroll
    for (int p3 = 0; p3 < 3; p3++) {
        int c = tid + p3*256;
        float s;
        if (t == 0) s = cls_token[c];
        else {
            int pr = b*NPAT + (t-1);
            s = conv_b[c] + pos_embed[(size_t)(t-1)*EE + c];
            #pragma unroll
            for (int p = 0; p < 3; p++) s += part[(size_t)p*(BB*NPAT)*EE + (size_t)pr*EE + c];
        }
        g_h[(size_t)r*EE + c] = s;
        v[p3] = s;
    }
    float mu = block_sum(v[0]+v[1]+v[2], red, tid) / EE;
    float sq = 0.f;
    #pragma unroll
    for (int p3 = 0; p3 < 3; p3++) { float d = v[p3]-mu; sq += d*d; }
    float inv = rsqrtf(block_sum(sq, red, tid) / EE + 1e-5f);
    #pragma unroll
    for (int p3 = 0; p3 < 3; p3++) {
        int c = tid + p3*256;
        g_lnh[(size_t)r*EE + c] = __float2half((v[p3]-mu)*inv*lw[c] + lb[c]);
    }
}

// ---------------- fused split-K reduce + bias + residual + optional LN (fp16 out) ----------------
template<int S, bool LNOUT>
__global__ void fuse_res_ln_kernel(const float* __restrict__ part, const float* __restrict__ bias,
                                   const float* __restrict__ lw, const float* __restrict__ lb) {
    int r = blockIdx.x;
    int tid = threadIdx.x;
    __shared__ float red[256];
    float v[3];
    #pragma unroll
    for (int p3 = 0; p3 < 3; p3++) {
        int c = tid + p3*256;
        float s = g_h[(size_t)r*EE + c] + bias[c];
        #pragma unroll
        for (int p = 0; p < S; p++) s += part[(size_t)p*MROWS*EE + (size_t)r*EE + c];
        g_h[(size_t)r*EE + c] = s;
        v[p3] = s;
    }
    if (!LNOUT) return;
    float mu = block_sum(v[0]+v[1]+v[2], red, tid) / EE;
    float sq = 0.f;
    #pragma unroll
    for (int p3 = 0; p3 < 3; p3++) { float d = v[p3]-mu; sq += d*d; }
    float inv = rsqrtf(block_sum(sq, red, tid) / EE + 1e-5f);
    #pragma unroll
    for (int p3 = 0; p3 < 3; p3++) {
        int c = tid + p3*256;
        g_lnh[(size_t)r*EE + c] = __float2half((v[p3]-mu)*inv*lw[c] + lb[c]);
    }
}

// ================= fp16 mma GEMM, 128x128x32 tile =================
// A: [M][K] fp16 row-major. B: [K][N] fp16 row-major.
// EPI=0: raw fp32 partials to C + z*M*N.
// EPI=1: v = gelu(acc + bias[gn]) stored fp16 to Cd (split 1).
// EPI=2: v = acc + bias[gn] stored fp32 to C (split 1).
template<int EPI>
__global__ __launch_bounds__(256, 2)
void mma_gemm(const __half* __restrict__ A, const __half* __restrict__ B,
              float* __restrict__ C, const float* __restrict__ bias, __half* __restrict__ Cd,
              int M, int N, int K, int klen) {
    __shared__ __half As[2][128*40];
    __shared__ __half Bs[2][32*136];

    int bn = blockIdx.x * 128;
    int bm = blockIdx.y * 128;
    int kz = blockIdx.z * klen;
    int tid = threadIdx.x;
    int lane = tid & 31;
    int w = tid >> 5;
    int wm = (w & 3) * 32;
    int wn = (w >> 2) * 64;

    int arow = tid >> 2;
    int acs  = (tid & 3) * 8;
    int brow = tid >> 4;
    int bcs  = (tid & 15) * 8;

    float acc[2][8][4];
    #pragma unroll
    for (int i = 0; i < 2; i++)
        #pragma unroll
        for (int j = 0; j < 8; j++)
            #pragma unroll
            for (int k = 0; k < 4; k++) acc[i][j][k] = 0.f;

    uint4 ra[2], rb[2];
    const uint4 zero4 = make_uint4(0, 0, 0, 0);

    auto fetch = [&](int kt) {
        int k0 = kz + kt * 32;
        #pragma unroll
        for (int p = 0; p < 2; p++) {
            int gm = bm + arow + p * 64;
            ra[p] = (gm < M) ? *(const uint4*)(A + (size_t)gm * K + k0 + acs) : zero4;
            rb[p] = *(const uint4*)(B + (size_t)(k0 + brow + p * 16) * N + bn + bcs);
        }
    };
    auto stash = [&](int b) {
        #pragma unroll
        for (int p = 0; p < 2; p++) {
            *(uint4*)&As[b][(arow + p * 64) * 40 + acs] = ra[p];
            *(uint4*)&Bs[b][(brow + p * 16) * 136 + bcs] = rb[p];
        }
    };

    fetch(0); stash(0); __syncthreads();
    int nk = klen >> 5;
    int buf = 0;
    for (int kt = 0; kt < nk; kt++) {
        if (kt + 1 < nk) fetch(kt + 1);
        #pragma unroll
        for (int s = 0; s < 2; s++) {
            uint32_t a[2][4], bf[8][2];
            #pragma unroll
            for (int mt = 0; mt < 2; mt++) {
                uint32_t ad = smaddr(&As[buf][(wm + mt*16 + (lane & 15))*40 + s*16 + (lane >> 4)*8]);
                ldsm_x4(a[mt][0], a[mt][1], a[mt][2], a[mt][3], ad);
            }
            #pragma unroll
            for (int h2 = 0; h2 < 4; h2++) {
                uint32_t ad = smaddr(&Bs[buf][(s*16 + (lane & 15))*136 + wn + h2*16 + (lane >> 4)*8]);
                ldsm_x4_t(bf[h2*2][0], bf[h2*2][1], bf[h2*2+1][0], bf[h2*2+1][1], ad);
            }
            #pragma unroll
            for (int mt = 0; mt < 2; mt++)
                #pragma unroll
                for (int nt = 0; nt < 8; nt++)
                    mma_f16(acc[mt][nt], a[mt], bf[nt][0], bf[nt][1]);
        }
        if (kt + 1 < nk) { buf ^= 1; stash(buf); __syncthreads(); }
    }

    float* Cz = (EPI == 1) ? nullptr : (C + (size_t)blockIdx.z * M * N);
    #pragma unroll
    for (int mt = 0; mt < 2; mt++) {
        int rbase = bm + wm + mt*16 + (lane >> 2);
        #pragma unroll
        for (int nt = 0; nt < 8; nt++) {
            int cbase = bn + wn + nt*8 + (lane & 3)*2;
            #pragma unroll
            for (int half = 0; half < 2; half++) {
                int gm = rbase + half*8;
                if (gm >= M) continue;
                #pragma unroll
                for (int e = 0; e < 2; e++) {
                    int gn = cbase + e;
                    float v = acc[mt][nt][half*2 + e];
                    if (EPI == 0) {
                        Cz[(size_t)gm * N + gn] = v;
                    } else if (EPI == 1) {
                        Cd[(size_t)gm * N + gn] = __float2half(gelu_tanh(v + bias[gn]));
                    } else {
                        Cz[(size_t)gm * N + gn] = v + bias[gn];
                    }
                }
            }
        }
    }
}

// ---------------- flash-style Tversky attention (reads fp32 qkv w/ bias, fp16 out) ----------------
__global__ __launch_bounds__(256)
void attn_flash_kernel(const float* __restrict__ qkv) {
    int it = blockIdx.x, h = blockIdx.y, b = blockIdx.z;
    int i0 = it * 64;
    __shared__ float Qs[64][68];
    __shared__ float Ks[64][36];
    __shared__ float Vs[32][68];
    __shared__ float Ps[64][36];
    __shared__ float qs_s[64], ks_s[32], den[64];
    int tid = threadIdx.x;

    #pragma unroll
    for (int p = 0; p < 4; p++) {
        int idx = tid + p*256;
        int i = idx >> 4, d4 = (idx & 15) * 4;
        int gi = i0 + i;
        float4 q = make_float4(0.f,0.f,0.f,0.f);
        if (gi < TT) q = *(const float4*)(qkv + (size_t)(b*TT + gi)*(3*EE) + h*DHH + d4);
        Qs[d4+0][i] = fmaxf(q.x, 0.f);
        Qs[d4+1][i] = fmaxf(q.y, 0.f);
        Qs[d4+2][i] = fmaxf(q.z, 0.f);
        Qs[d4+3][i] = fmaxf(q.w, 0.f);
    }
    if (tid < 64) den[tid] = 0.f;
    __syncthreads();
    if (tid < 64) {
        float s = 0.f;
        #pragma unroll
        for (int d = 0; d < 64; d++) s += Qs[d][tid];
        qs_s[tid] = s;
    }

    float o[4][4];
    #pragma unroll
    for (int r = 0; r < 4; r++)
        #pragma unroll
        for (int c = 0; c < 4; c++) o[r][c] = 0.f;

    int tj = tid & 15, ti = tid >> 4;

    for (int jc = 0; jc < 7; jc++) {
        int j0 = jc * 32;
        __syncthreads();
        #pragma unroll
        for (int p = 0; p < 2; p++) {
            int idx = tid + p*256;
            int j = idx >> 4, d4 = (idx & 15) * 4;
            int gj = j0 + j;
            float4 kv = make_float4(0.f,0.f,0.f,0.f);
            float4 vv = make_float4(0.f,0.f,0.f,0.f);
            if (gj < TT) {
                const float* rowp = qkv + (size_t)(b*TT + gj)*(3*EE) + h*DHH + d4;
                kv = *(const float4*)(rowp + EE);
                vv = *(const float4*)(rowp + 2*EE);
            }
            Ks[d4+0][j] = fmaxf(kv.x, 0.f);
            Ks[d4+1][j] = fmaxf(kv.y, 0.f);
            Ks[d4+2][j] = fmaxf(kv.z, 0.f);
            Ks[d4+3][j] = fmaxf(kv.w, 0.f);
            *(float4*)&Vs[j][d4] = vv;
        }
        __syncthreads();
        if (tid < 32) {
            float s = 0.f;
            #pragma unroll
            for (int d = 0; d < 64; d++) s += Ks[d][tid];
            ks_s[tid] = s;
        }
        __syncthreads();

        float m[4][2];
        #pragma unroll
        for (int r = 0; r < 4; r++) { m[r][0] = 0.f; m[r][1] = 0.f; }
        #pragma unroll 8
        for (int d = 0; d < 64; d++) {
            float4 qv = *(const float4*)&Qs[d][ti*4];
            float2 kv = *(const float2*)&Ks[d][tj*2];
            m[0][0] += fminf(qv.x, kv.x); m[0][1] += fminf(qv.x, kv.y);
            m[1][0] += fminf(qv.y, kv.x); m[1][1] += fminf(qv.y, kv.y);
            m[2][0] += fminf(qv.z, kv.x); m[2][1] += fminf(qv.z, kv.y);
            m[3][0] += fminf(qv.w, kv.x); m[3][1] += fminf(qv.w, kv.y);
        }
        #pragma unroll
        for (int r = 0; r < 4; r++) {
            int i = ti*4 + r;
            int gi = i0 + i;
            #pragma unroll
            for (int e = 0; e < 2; e++) {
                int j = tj*2 + e;
                int gj = j0 + j;
                float sc = 2.f * m[r][e] / (qs_s[i] + ks_s[j] + 2e-8f);
                Ps[i][j] = (gi < TT && gj < TT) ? expf(sc) : 0.f;
            }
        }
        __syncthreads();
        if (tid < 64) {
            float s = 0.f;
            #pragma unroll
            for (int j = 0; j < 32; j++) s += Ps[tid][j];
            den[tid] += s;
        }
        #pragma unroll 4
        for (int jj = 0; jj < 32; jj++) {
            float4 vv = *(const float4*)&Vs[jj][tj*4];
            #pragma unroll
            for (int r = 0; r < 4; r++) {
                float pw = Ps[ti*4 + r][jj];
                o[r][0] += pw * vv.x;
                o[r][1] += pw * vv.y;
                o[r][2] += pw * vv.z;
                o[r][3] += pw * vv.w;
            }
        }
    }
    __syncthreads();

    #pragma unroll
    for (int r = 0; r < 4; r++) {
        int i = ti*4 + r;
        int gi = i0 + i;
        if (gi >= TT) continue;
        float dn = den[i];
        __half* op = g_act + (size_t)(b*TT + gi) * EE + h*DHH;
        #pragma unroll
        for (int c = 0; c < 4; c++)
            op[tj*4 + c] = __float2half(o[r][c] / dn);
    }
}

// ---------------- merged final LN (cls rows) + head GEMM ----------------
__global__ void head_ln_kernel(const float* __restrict__ lw, const float* __restrict__ lb,
                               const float* __restrict__ B, const float* __restrict__ bias,
                               float* __restrict__ C) {
    const int BN = 64, BK = 16, M = BB, N = OUTC, K = EE;
    __shared__ float Afull[BB][EE];   // 12 KB (LN'd cls rows)
    __shared__ float Bs[BK][BN + 1];
    __shared__ float red[256];
    int bn = blockIdx.x * BN;
    int tid = threadIdx.x;
    int tx = tid & 15, ty = tid >> 4;

    // LN the 4 cls rows into smem (replicated per block; cheap)
    for (int b = 0; b < BB; b++) {
        const float* x = g_h + (size_t)(b*TT) * EE;
        float s = 0.f;
        for (int c = tid; c < EE; c += 256) s += x[c];
        float mu = block_sum(s, red, tid) / EE;
        float s2 = 0.f;
        for (int c = tid; c < EE; c += 256) { float d = x[c]-mu; s2 += d*d; }
        float inv = rsqrtf(block_sum(s2, red, tid) / EE + 1e-5f);
        for (int c = tid; c < EE; c += 256)
            Afull[b][c] = (x[c]-mu)*inv*lw[c] + lb[c];
    }
    __syncthreads();

    float acc[4] = {0.f, 0.f, 0.f, 0.f};
    for (int k0 = 0; k0 < K; k0 += BK) {
        #pragma unroll
        for (int i = 0; i < 4; i++) {
            int s = tid + i * 256;
            int kk = s >> 6, n = s & 63;
            int gn = bn + n;
            Bs[kk][n] = (gn < N) ? B[(size_t)(k0 + kk) * N + gn] : 0.f;
        }
        __syncthreads();
        if (ty < M) {
            #pragma unroll
            for (int kk = 0; kk < BK; kk++) {
                float a = Afull[ty][k0 + kk];
                #pragma unroll
                for (int j = 0; j < 4; j++)
                    acc[j] = fmaf(a, Bs[kk][tx*4 + j], acc[j]);
            }
        }
        __syncthreads();
    }
    if (ty < M) {
        #pragma unroll
        for (int j = 0; j < 4; j++) {
            int gn = bn + tx*4 + j;
            if (gn < N) C[(size_t)ty * N + gn] = acc[j] + bias[gn];
        }
    }
}

// ---------------- host launcher ----------------
extern "C" void kernel_launch(void* const* d_in, const int* in_sizes, int n_in,
                              void* d_out, int out_size) {
    const float* x         = (const float*)d_in[0];
    const float* conv_w    = (const float*)d_in[1];
    const float* conv_b    = (const float*)d_in[2];
    const float* pos_embed = (const float*)d_in[3];
    const float* cls_token = (const float*)d_in[4];
    const float* ln1_w     = (const float*)d_in[5];
    const float* ln1_b     = (const float*)d_in[6];
    const float* attn_w    = (const float*)d_in[7];
    const float* attn_b    = (const float*)d_in[8];
    const float* proj_w    = (const float*)d_in[9];
    const float* proj_b    = (const float*)d_in[10];
    const float* ln2_w     = (const float*)d_in[11];
    const float* ln2_b     = (const float*)d_in[12];
    const float* fc1_w     = (const float*)d_in[13];
    const float* fc1_b     = (const float*)d_in[14];
    const float* fc2_w     = (const float*)d_in[15];
    const float* fc2_b     = (const float*)d_in[16];
    const float* lnf_w     = (const float*)d_in[17];
    const float* lnf_b     = (const float*)d_in[18];
    const float* head_w    = (const float*)d_in[19];
    const float* head_b    = (const float*)d_in[20];
    float* out = (float*)d_out;

    float *p_part;
    __half *p_act, *p_lnh, *p_wh;
    cudaGetSymbolAddress((void**)&p_part, g_part);
    cudaGetSymbolAddress((void**)&p_act, g_act);
    cudaGetSymbolAddress((void**)&p_lnh, g_lnh);
    cudaGetSymbolAddress((void**)&p_wh, g_wh);

    const __half* wPatch = p_wh;
    const __half* wQKV[LL], *wProj[LL], *wFc1[LL], *wFc2[LL];
    for (int l = 0; l < LL; l++) {
        const __half* base = p_wh + SZ_PATCH_H + (size_t)l * SZ_LAYER_H;
        wQKV[l] = base;
        wProj[l] = base + SZ_QKV_H;
        wFc1[l] = base + SZ_QKV_H + SZ_PROJ_H;
        wFc2[l] = base + SZ_QKV_H + SZ_PROJ_H + SZ_FC1_H;
    }

    // ---- merged prep: im2col + all weight conversion ----
    {
        int total = IM2COL_TOTAL + W_TOTAL_H;
        prep_kernel<<<(total + 255)/256, 256>>>(x, conv_w, attn_w, proj_w, fc1_w, fc2_w);
    }

    // ---- patch embedding GEMM (split-3) + fused epilogue/LN1 ----
    {
        dim3 g(EE/128, (BB*NPAT + 127)/128, 3);
        mma_gemm<0><<<g, 256>>>(p_act, wPatch, p_part, nullptr, nullptr,
                                BB*NPAT, EE, KPATCH, KPATCH/3);
        patch_ln_kernel<<<MROWS, 256>>>(p_part, conv_b, pos_embed, cls_token, ln1_w, ln1_b);
    }

    // ---- transformer layers ----
    for (int l = 0; l < LL; l++) {
        const float* ab  = attn_b + (size_t)l * 3 * EE;
        const float* pb  = proj_b + (size_t)l * EE;
        const float* lw2 = ln2_w + (size_t)l * EE;
        const float* lb2 = ln2_b + (size_t)l * EE;
        const float* f1b = fc1_b + (size_t)l * DFF_;
        const float* f2b = fc2_b + (size_t)l * EE;

        // qkv: split-1, fused bias, fp32 direct -> g_part (attention reads it)
        {
            dim3 g((3*EE)/128, (MROWS + 127)/128, 1);
            mma_gemm<2><<<g, 256>>>(p_lnh, wQKV[l], p_part, ab, nullptr,
                                    MROWS, 3*EE, EE, EE);
        }
        attn_flash_kernel<<<dim3(4, NHH, BB), 256>>>(p_part);
        // proj: split-3 + fused reduce/res/LN2
        {
            dim3 g(EE/128, (MROWS + 127)/128, 3);
            mma_gemm<0><<<g, 256>>>(p_act, wProj[l], p_part, nullptr, nullptr,
                                    MROWS, EE, EE, EE/3);
            fuse_res_ln_kernel<3, true><<<MROWS, 256>>>(p_part, pb, lw2, lb2);
        }
        // fc1: split-1, fused gelu+bias epilogue -> g_act (fp16)
        {
            dim3 g(DFF_/128, (MROWS + 127)/128, 1);
            mma_gemm<1><<<g, 256>>>(p_lnh, wFc1[l], nullptr, f1b, p_act,
                                    MROWS, DFF_, EE, EE);
        }
        // fc2: split-2 + fused reduce/res (+ LN1 of next layer)
        {
            dim3 g(EE/128, (MROWS + 127)/128, 2);
            mma_gemm<0><<<g, 256>>>(p_act, wFc2[l], p_part, nullptr, nullptr,
                                    MROWS, EE, DFF_, DFF_/2);
            if (l + 1 < LL) {
                fuse_res_ln_kernel<2, true><<<MROWS, 256>>>(
                    p_part, f2b, ln1_w + (size_t)(l+1)*EE, ln1_b + (size_t)(l+1)*EE);
            } else {
                fuse_res_ln_kernel<2, false><<<MROWS, 256>>>(p_part, f2b, nullptr, nullptr);
            }
        }
    }

    // ---- merged final LN (cls rows) + head ----
    head_ln_kernel<<<(OUTC + 63)/64, 256>>>(lnf_w, lnf_b, head_w, head_b, out);
}